// round 11
// baseline (speedup 1.0000x reference)
#include <cuda_runtime.h>
#include <cuda_fp16.h>
#include <cstdint>
#include <math.h>

#define Bsz 32
#define Tn  128
#define Nn  47
#define CIN 192
#define COUT 256
#define KK  3

#define NT   512          // k_gemm threads (16 warps)

#define XS_PITCH 200   // halves per t-row (192 + pad)
#define BS_PITCH 40    // halves per col-row (32 k + pad)

#define XS_BYTES (128 * XS_PITCH * 2)                 // 51200
#define BS_HALF  (256 * BS_PITCH * 2)                 // 20480 per buffer
#define BS_BYTES (2 * BS_HALF)                        // 40960
#define SMEM_GEMM (XS_BYTES + BS_BYTES)               // 92160

#define HP_PITCH 130                                   // halves per channel row in k_post smem
#define SMEM_POST (256 * HP_PITCH * 2)                 // 66560

// ---------------- scratch ----------------
__device__ __align__(256) __half g_wh[(size_t)Nn * 512 * CIN];          // [n][j][c]
__device__ __align__(256) __half g_h16[(size_t)Bsz * Nn * Tn * COUT];   // [b][n][t][c]
__device__ __align__(256) __half g_res16[(size_t)Bsz * Nn * Tn * COUT]; // [b][n][t][c]

// ---------------- K1: rowsum (in-block) + fused fp16 weights, 8-wide ----------------
__global__ void __launch_bounds__(256) k_wh(const float* __restrict__ A, const float* __restrict__ adj,
                                            const float* __restrict__ dw, const float* __restrict__ Wpw,
                                            const float* __restrict__ Wres) {
    __shared__ float srs[KK][2];
    const int idx8_0 = blockIdx.x * 256;
    const int n0 = idx8_0 / (24 * 512);
    const int warp = threadIdx.x >> 5, lane = threadIdx.x & 31;
    if (warp < 6) {
        int k = warp % KK, nn = n0 + warp / KK;
        if (nn < Nn) {
            const float* ar = A   + ((size_t)k * Nn + nn) * Nn;
            const float* rr = adj + ((size_t)k * Nn + nn) * Nn;
            float s = 0.f, sa = 0.f;
            for (int m = lane; m < Nn; m += 32) {
                float v = ar[m] + 0.3f * tanhf(rr[m]);
                s += v; sa += fabsf(v);
            }
#pragma unroll
            for (int o = 16; o; o >>= 1) {
                s  += __shfl_xor_sync(0xFFFFFFFFu, s,  o);
                sa += __shfl_xor_sync(0xFFFFFFFFu, sa, o);
            }
            if (lane == 0) srs[k][warp / KK] = s / fmaxf(sa, 1.0f);
        }
    }
    __syncthreads();

    const int idx8 = idx8_0 + threadIdx.x;
    if (idx8 >= Nn * 512 * 24) return;
    const int c0 = (idx8 % 24) * 8;
    const int j  = (idx8 / 24) & 511;
    const int n  = idx8 / (24 * 512);
    float w8[8];
    if (j < COUT) {
#pragma unroll
        for (int i = 0; i < 8; i++) w8[i] = 0.f;
#pragma unroll
        for (int k = 0; k < KK; k++) {
            float rs = srs[k][n - n0];
            const float* dwp = dw + k * CIN + c0;
            const float* wp  = Wpw + (size_t)j * (KK * CIN) + k * CIN + c0;
            float4 d0 = *(const float4*)dwp, d1 = *(const float4*)(dwp + 4);
            float4 p0 = *(const float4*)wp,  p1 = *(const float4*)(wp + 4);
            w8[0] += rs * d0.x * p0.x; w8[1] += rs * d0.y * p0.y;
            w8[2] += rs * d0.z * p0.z; w8[3] += rs * d0.w * p0.w;
            w8[4] += rs * d1.x * p1.x; w8[5] += rs * d1.y * p1.y;
            w8[6] += rs * d1.z * p1.z; w8[7] += rs * d1.w * p1.w;
        }
    } else {
        const float* rp = Wres + (size_t)(j - COUT) * CIN + c0;
        float4 r0 = *(const float4*)rp, r1 = *(const float4*)(rp + 4);
        w8[0] = r0.x; w8[1] = r0.y; w8[2] = r0.z; w8[3] = r0.w;
        w8[4] = r1.x; w8[5] = r1.y; w8[6] = r1.z; w8[7] = r1.w;
    }
    __half2 h2[4];
#pragma unroll
    for (int i = 0; i < 4; i++) h2[i] = __floats2half2_rn(w8[2 * i], w8[2 * i + 1]);
    *(uint4*)(g_wh + (size_t)idx8 * 8) = *(const uint4*)h2;
}

// ---------------- helpers ----------------
__device__ __forceinline__ void cp_async16(uint32_t dst, const void* src) {
    asm volatile("cp.async.cg.shared.global [%0], [%1], 16;\n" :: "r"(dst), "l"(src));
}
__device__ __forceinline__ void mma16816(float* d, const uint32_t* a, const uint32_t* b) {
    asm volatile(
        "mma.sync.aligned.m16n8k16.row.col.f32.f16.f16.f32 "
        "{%0,%1,%2,%3}, {%4,%5,%6,%7}, {%8,%9}, {%0,%1,%2,%3};\n"
        : "+f"(d[0]), "+f"(d[1]), "+f"(d[2]), "+f"(d[3])
        : "r"(a[0]), "r"(a[1]), "r"(a[2]), "r"(a[3]), "r"(b[0]), "r"(b[1]));
}
__device__ __forceinline__ void ldsm_x4(uint32_t& r0, uint32_t& r1, uint32_t& r2, uint32_t& r3,
                                        uint32_t addr) {
    asm volatile("ldmatrix.sync.aligned.m8n8.x4.shared.b16 {%0,%1,%2,%3}, [%4];"
                 : "=r"(r0), "=r"(r1), "=r"(r2), "=r"(r3) : "r"(addr));
}
__device__ __forceinline__ float gelu_exact(float v) {
    return 0.5f * v * (1.f + erff(v * 0.70710678118654752f));
}

// ---------------- K2: per-(b,n) dual GEMM -> fp16 h/res to global ----------------
__global__ void __launch_bounds__(NT, 1)
k_gemm(const float* __restrict__ x) {
    extern __shared__ char sm[];
    __half* xs = (__half*)sm;                           // [128][200] halves
    __half* bs = (__half*)(sm + XS_BYTES);              // 2 x [256][40] halves

    const int n = blockIdx.x, b = blockIdx.y;
    const int tid  = threadIdx.x;
    const int lane = tid & 31, warp = tid >> 5;
    const int g = lane >> 2, q = lane & 3;
    const int wm = warp & 1, wn = warp >> 1;            // 2 x 8 warp grid

    const __half* wbase = g_wh + (size_t)n * 512 * CIN;

    const uint32_t xs_u32 = (uint32_t)__cvta_generic_to_shared(xs);
    const uint32_t bs_u32 = (uint32_t)__cvta_generic_to_shared(bs);

    const int a_row_off = (lane & 7) + ((lane >> 3) & 1) * 8;
    const int a_k_off   = ((lane >> 4) & 1) * 8;
    uint32_t addrA[4];
#pragma unroll
    for (int mi = 0; mi < 4; mi++)
        addrA[mi] = xs_u32 + (uint32_t)((wm * 64 + mi * 16 + a_row_off) * (XS_PITCH * 2) + a_k_off * 2);
    const int b_n_off = ((lane >> 4) & 1) * 8 + (lane & 7);
    const int b_k_off = ((lane >> 3) & 1) * 8;
    uint32_t addrB[2];
#pragma unroll
    for (int pp = 0; pp < 2; pp++)
        addrB[pp] = bs_u32 + (uint32_t)((wn * 32 + pp * 16 + b_n_off) * (BS_PITCH * 2) + b_k_off * 2);

    auto stage = [&](int p, int kc, int buf) {
        int col = tid >> 1, hv = tid & 1;
        const __half* src = wbase + (size_t)(p * 256 + col) * CIN + kc * 32 + hv * 16;
        uint32_t d = bs_u32 + (uint32_t)(buf * BS_HALF + col * (BS_PITCH * 2) + hv * 32);
        cp_async16(d,      src);
        cp_async16(d + 16, src + 8);
        asm volatile("cp.async.commit_group;\n");
    };

    // ---- load x tile -> fp16 smem (overlap with first B stage) ----
    stage(0, 0, 0);
    for (int i = tid; i < 128 * 48; i += NT) {
        int t = i / 48, c4 = (i % 48) * 4;
        float4 v = *(const float4*)(x + ((size_t)(b * Tn + t) * Nn + n) * CIN + c4);
        __half2* dst = (__half2*)(xs + t * XS_PITCH + c4);
        dst[0] = __floats2half2_rn(v.x, v.y);
        dst[1] = __floats2half2_rn(v.z, v.w);
    }
    __syncthreads();

    float acc[4][4][4];
    __half* outbuf[2] = { g_h16, g_res16 };

#pragma unroll 1
    for (int p = 0; p < 2; p++) {
#pragma unroll
        for (int mi = 0; mi < 4; mi++)
#pragma unroll
            for (int ni = 0; ni < 4; ni++)
#pragma unroll
                for (int r = 0; r < 4; r++) acc[mi][ni][r] = 0.f;

        if (p == 1) stage(1, 0, 0);

#pragma unroll 1
        for (int kc = 0; kc < 6; kc++) {
            if (kc < 5) {
                stage(p, kc + 1, (kc + 1) & 1);
                asm volatile("cp.async.wait_group 1;\n");
            } else {
                asm volatile("cp.async.wait_group 0;\n");
            }
            __syncthreads();
            const uint32_t bsel = (uint32_t)((kc & 1) * BS_HALF);
#pragma unroll
            for (int ks = 0; ks < 2; ks++) {
                const uint32_t kbb = (uint32_t)((kc * 32 + ks * 16) * 2);
                uint32_t afr[4][4];
                uint32_t bfr[4][2];
#pragma unroll
                for (int mi = 0; mi < 4; mi++)
                    ldsm_x4(afr[mi][0], afr[mi][1], afr[mi][2], afr[mi][3], addrA[mi] + kbb);
#pragma unroll
                for (int pp = 0; pp < 2; pp++)
                    ldsm_x4(bfr[pp * 2][0], bfr[pp * 2][1], bfr[pp * 2 + 1][0], bfr[pp * 2 + 1][1],
                            addrB[pp] + bsel + (uint32_t)(ks * 32));
#pragma unroll
                for (int ni = 0; ni < 4; ni++)
#pragma unroll
                    for (int mi = 0; mi < 4; mi++)
                        mma16816(acc[mi][ni], afr[mi], bfr[ni]);
            }
            __syncthreads();
        }

        // ---- epilogue: fp16 store [b][n][t][c] ----
        __half* dst = outbuf[p] + ((size_t)(b * Nn + n) * Tn) * COUT;
#pragma unroll
        for (int mi = 0; mi < 4; mi++) {
#pragma unroll
            for (int half = 0; half < 2; half++) {
                int t = wm * 64 + mi * 16 + g + half * 8;
                __half* row = dst + (size_t)t * COUT;
                int r = half * 2;
#pragma unroll
                for (int ni = 0; ni < 4; ni++) {
                    int o0 = wn * 32 + ni * 8 + 2 * q;
                    *(__half2*)(row + o0) = __floats2half2_rn(acc[mi][ni][r], acc[mi][ni][r + 1]);
                }
            }
        }
    }
}

// ---------------- K3: conv + GN + LN + GELU, high occupancy ----------------
__global__ void __launch_bounds__(256)
k_post(const float* __restrict__ convw,
       const float* __restrict__ gng, const float* __restrict__ gnb,
       const float* __restrict__ lng, const float* __restrict__ lnb,
       float* __restrict__ out) {
    extern __shared__ __half hbuf[];       // [256][HP_PITCH] halves
    __shared__ float chA[256], chB[256];

    const int n = blockIdx.x, b = blockIdx.y;
    const int tid = threadIdx.x;
    const int lane = tid & 31, warp = tid >> 5;

    // ---- phase 1: temporal conv (thread = channel, coalesced global reads) ----
    const int o = tid;
    const __half* hsrc = g_h16 + ((size_t)(b * Nn + n) * Tn) * COUT + o;
    const float w0 = convw[o * 3], w1 = convw[o * 3 + 1], w2 = convw[o * 3 + 2];
    float prev = 0.f, cur = __half2float(hsrc[0]);
    float s = 0.f, s2 = 0.f;
    __half* hrow = hbuf + o * HP_PITCH;
#pragma unroll 4
    for (int t = 0; t < Tn; t++) {
        float nxt = (t < Tn - 1) ? __half2float(hsrc[(size_t)(t + 1) * COUT]) : 0.f;
        float v = w0 * prev + w1 * cur + w2 * nxt;
        hrow[t] = __float2half_rn(v);
        s += v; s2 += v * v;
        prev = cur; cur = nxt;
    }
    // GN group == warp (32 consecutive channels)
#pragma unroll
    for (int off = 16; off; off >>= 1) {
        s  += __shfl_xor_sync(0xFFFFFFFFu, s,  off);
        s2 += __shfl_xor_sync(0xFFFFFFFFu, s2, off);
    }
    const float inv = 1.f / (32.f * Tn);
    float mu = s * inv;
    float var = s2 * inv - mu * mu;
    float rstd = rsqrtf(var + 1e-5f);
    float ga = gng[o] * rstd;
    chA[o] = ga;
    chB[o] = gnb[o] - mu * ga;
    __syncthreads();

    // ---- phase 2: LN over 256 ch per t (+res) + GELU ----
    float lg[8], lb[8];
#pragma unroll
    for (int j = 0; j < 8; j++) { lg[j] = lng[lane + 32 * j]; lb[j] = lnb[lane + 32 * j]; }
    const __half* resb = g_res16 + ((size_t)(b * Nn + n) * Tn) * COUT;

    for (int t = warp; t < Tn; t += 8) {
        float y[8]; float su = 0.f, sq = 0.f;
#pragma unroll
        for (int j = 0; j < 8; j++) {
            int c = lane + 32 * j;
            float v = __half2float(hbuf[c * HP_PITCH + t]) * chA[c] + chB[c]
                    + __half2float(resb[(size_t)t * COUT + c]);
            y[j] = v; su += v; sq += v * v;
        }
#pragma unroll
        for (int off = 16; off; off >>= 1) {
            su += __shfl_xor_sync(0xFFFFFFFFu, su, off);
            sq += __shfl_xor_sync(0xFFFFFFFFu, sq, off);
        }
        float m2 = su * (1.f / 256.f);
        float vr = sq * (1.f / 256.f) - m2 * m2;
        float rs = rsqrtf(vr + 1e-5f);
        float* ob = out + ((size_t)(b * Tn + t) * Nn + n) * COUT;
#pragma unroll
        for (int j = 0; j < 8; j++) {
            float v = (y[j] - m2) * rs * lg[j] + lb[j];
            ob[lane + 32 * j] = gelu_exact(v);
        }
    }
}

// ---------------- launch ----------------
extern "C" void kernel_launch(void* const* d_in, const int* in_sizes, int n_in,
                              void* d_out, int out_size) {
    const float* x     = (const float*)d_in[0];
    const float* A     = (const float*)d_in[1];
    const float* dw    = (const float*)d_in[2];
    const float* adj   = (const float*)d_in[3];
    const float* Wpw   = (const float*)d_in[4];
    const float* convw = (const float*)d_in[5];
    const float* gng   = (const float*)d_in[6];
    const float* gnb   = (const float*)d_in[7];
    const float* lng   = (const float*)d_in[8];
    const float* lnb   = (const float*)d_in[9];
    const float* Wres  = (const float*)d_in[10];
    float* out = (float*)d_out;

    cudaFuncSetAttribute(k_gemm, cudaFuncAttributeMaxDynamicSharedMemorySize, SMEM_GEMM);
    cudaFuncSetAttribute(k_post, cudaFuncAttributeMaxDynamicSharedMemorySize, SMEM_POST);

    int total8 = Nn * 512 * 24;
    k_wh<<<(total8 + 255) / 256, 256>>>(A, adj, dw, Wpw, Wres);
    k_gemm<<<dim3(Nn, Bsz), NT, SMEM_GEMM>>>(x);
    k_post<<<dim3(Nn, Bsz), 256, SMEM_POST>>>(convw, gng, gnb, lng, lnb, out);
}

// round 12
// speedup vs baseline: 1.3444x; 1.3444x over previous
#include <cuda_runtime.h>
#include <cuda_fp16.h>
#include <cstdint>
#include <math.h>

#define Bsz 32
#define Tn  128
#define Nn  47
#define CIN 192
#define COUT 256
#define KK  3

#define NT   512          // threads per block (16 warps)

#define XS_PITCH 200   // halves per t-row (192 + pad)
#define HB_PITCH 264   // floats per t-row (256 + pad)
#define BS_PITCH 40    // halves per col-row (32 k + pad)

#define XS_BYTES (128 * XS_PITCH * 2)                 // 51200
#define HB_BYTES (128 * HB_PITCH * 4)                 // 135168
#define BS_HALF  (256 * BS_PITCH * 2)                 // 20480 per buffer
#define BS_BYTES (2 * BS_HALF)                        // 40960
#define SMEM_TOTAL (XS_BYTES + HB_BYTES + BS_BYTES)   // 227328

// ---------------- scratch ----------------
__device__ __align__(256) __half g_wh[(size_t)Nn * 512 * CIN];  // [n][j][c]

// ---------------- K1: rowsum (in-block) + fused fp16 weights, 8-wide ----------------
__global__ void __launch_bounds__(256) k_wh(const float* __restrict__ A, const float* __restrict__ adj,
                                            const float* __restrict__ dw, const float* __restrict__ Wpw,
                                            const float* __restrict__ Wres) {
    __shared__ float srs[KK][2];
    const int idx8_0 = blockIdx.x * 256;
    const int n0 = idx8_0 / (24 * 512);
    const int warp = threadIdx.x >> 5, lane = threadIdx.x & 31;
    if (warp < 6) {
        int k = warp % KK, nn = n0 + warp / KK;
        if (nn < Nn) {
            const float* ar = A   + ((size_t)k * Nn + nn) * Nn;
            const float* rr = adj + ((size_t)k * Nn + nn) * Nn;
            float s = 0.f, sa = 0.f;
            for (int m = lane; m < Nn; m += 32) {
                float v = ar[m] + 0.3f * tanhf(rr[m]);
                s += v; sa += fabsf(v);
            }
#pragma unroll
            for (int o = 16; o; o >>= 1) {
                s  += __shfl_xor_sync(0xFFFFFFFFu, s,  o);
                sa += __shfl_xor_sync(0xFFFFFFFFu, sa, o);
            }
            if (lane == 0) srs[k][warp / KK] = s / fmaxf(sa, 1.0f);
        }
    }
    __syncthreads();

    const int idx8 = idx8_0 + threadIdx.x;
    if (idx8 >= Nn * 512 * 24) return;
    const int c0 = (idx8 % 24) * 8;
    const int j  = (idx8 / 24) & 511;
    const int n  = idx8 / (24 * 512);
    float w8[8];
    if (j < COUT) {
#pragma unroll
        for (int i = 0; i < 8; i++) w8[i] = 0.f;
#pragma unroll
        for (int k = 0; k < KK; k++) {
            float rs = srs[k][n - n0];
            const float* dwp = dw + k * CIN + c0;
            const float* wp  = Wpw + (size_t)j * (KK * CIN) + k * CIN + c0;
            float4 d0 = *(const float4*)dwp, d1 = *(const float4*)(dwp + 4);
            float4 p0 = *(const float4*)wp,  p1 = *(const float4*)(wp + 4);
            w8[0] += rs * d0.x * p0.x; w8[1] += rs * d0.y * p0.y;
            w8[2] += rs * d0.z * p0.z; w8[3] += rs * d0.w * p0.w;
            w8[4] += rs * d1.x * p1.x; w8[5] += rs * d1.y * p1.y;
            w8[6] += rs * d1.z * p1.z; w8[7] += rs * d1.w * p1.w;
        }
    } else {
        const float* rp = Wres + (size_t)(j - COUT) * CIN + c0;
        float4 r0 = *(const float4*)rp, r1 = *(const float4*)(rp + 4);
        w8[0] = r0.x; w8[1] = r0.y; w8[2] = r0.z; w8[3] = r0.w;
        w8[4] = r1.x; w8[5] = r1.y; w8[6] = r1.z; w8[7] = r1.w;
    }
    __half2 h2[4];
#pragma unroll
    for (int i = 0; i < 4; i++) h2[i] = __floats2half2_rn(w8[2 * i], w8[2 * i + 1]);
    *(uint4*)(g_wh + (size_t)idx8 * 8) = *(const uint4*)h2;
}

// ---------------- helpers ----------------
__device__ __forceinline__ void cp_async16(uint32_t dst, const void* src) {
    asm volatile("cp.async.cg.shared.global [%0], [%1], 16;\n" :: "r"(dst), "l"(src));
}
__device__ __forceinline__ void mma16816(float* d, const uint32_t* a, const uint32_t* b) {
    asm volatile(
        "mma.sync.aligned.m16n8k16.row.col.f32.f16.f16.f32 "
        "{%0,%1,%2,%3}, {%4,%5,%6,%7}, {%8,%9}, {%0,%1,%2,%3};\n"
        : "+f"(d[0]), "+f"(d[1]), "+f"(d[2]), "+f"(d[3])
        : "r"(a[0]), "r"(a[1]), "r"(a[2]), "r"(a[3]), "r"(b[0]), "r"(b[1]));
}
__device__ __forceinline__ void ldsm_x4(uint32_t& r0, uint32_t& r1, uint32_t& r2, uint32_t& r3,
                                        uint32_t addr) {
    asm volatile("ldmatrix.sync.aligned.m8n8.x4.shared.b16 {%0,%1,%2,%3}, [%4];"
                 : "=r"(r0), "=r"(r1), "=r"(r2), "=r"(r3) : "r"(addr));
}
// branch-free GELU: Abramowitz-Stegun 7.1.26 erf (|err| <= 1.5e-7)
__device__ __forceinline__ float gelu_fast(float v) {
    float x  = v * 0.70710678118654752f;
    float ax = fabsf(x);
    float t  = __fdividef(1.0f, fmaf(0.3275911f, ax, 1.0f));
    float p  = fmaf(fmaf(fmaf(fmaf(1.061405429f, t, -1.453152027f), t, 1.421413741f),
                         t, -0.284496736f), t, 0.254829592f);
    float e  = __expf(-ax * ax);
    float er = fmaf(-p * t, e, 1.0f);           // erf(|x|)
    er = copysignf(er, x);
    return 0.5f * v * (1.0f + er);
}

// ---------------- K2: fused per-(b,n) block; conv overlapped into p1 GEMM ----------------
__global__ void __launch_bounds__(NT, 1)
k_fused(const float* __restrict__ x, const float* __restrict__ convw,
        const float* __restrict__ gng, const float* __restrict__ gnb,
        const float* __restrict__ lng, const float* __restrict__ lnb,
        float* __restrict__ out) {
    extern __shared__ char sm[];
    __half* xs   = (__half*)sm;                         // [128][200] halves
    float*  hbuf = (float*)(sm + XS_BYTES);             // [128][264] floats
    __half* bs   = (__half*)(sm + XS_BYTES + HB_BYTES); // 2 x [256][40] halves
    float* part   = (float*)(sm + XS_BYTES + HB_BYTES); // aliases bs buf0 (dead by fold): [128][8][2]
    float* lnstat = part + 2048;                        // [128][2]
    __shared__ float s_gn[16][2];
    __shared__ float chA[256], chB[256];

    const int n = blockIdx.x, b = blockIdx.y;
    const int tid  = threadIdx.x;
    const int lane = tid & 31, warp = tid >> 5;
    const int g = lane >> 2, q = lane & 3;
    const int wm = warp & 1, wn = warp >> 1;            // 2 x 8 warp grid

    const __half* wbase = g_wh + (size_t)n * 512 * CIN;

    const uint32_t xs_u32 = (uint32_t)__cvta_generic_to_shared(xs);
    const uint32_t bs_u32 = (uint32_t)__cvta_generic_to_shared(bs);

    const int a_row_off = (lane & 7) + ((lane >> 3) & 1) * 8;
    const int a_k_off   = ((lane >> 4) & 1) * 8;
    uint32_t addrA[4];
#pragma unroll
    for (int mi = 0; mi < 4; mi++)
        addrA[mi] = xs_u32 + (uint32_t)((wm * 64 + mi * 16 + a_row_off) * (XS_PITCH * 2) + a_k_off * 2);
    const int b_n_off = ((lane >> 4) & 1) * 8 + (lane & 7);
    const int b_k_off = ((lane >> 3) & 1) * 8;
    uint32_t addrB[2];
#pragma unroll
    for (int pp = 0; pp < 2; pp++)
        addrB[pp] = bs_u32 + (uint32_t)((wn * 32 + pp * 16 + b_n_off) * (BS_PITCH * 2) + b_k_off * 2);

    auto stage = [&](int p, int kc, int buf) {
        int col = tid >> 1, hv = tid & 1;
        const __half* src = wbase + (size_t)(p * 256 + col) * CIN + kc * 32 + hv * 16;
        uint32_t d = bs_u32 + (uint32_t)(buf * BS_HALF + col * (BS_PITCH * 2) + hv * 32);
        cp_async16(d,      src);
        cp_async16(d + 16, src + 8);
        asm volatile("cp.async.commit_group;\n");
    };

    // ---- load x tile -> fp16 smem (overlap with first B stage) ----
    stage(0, 0, 0);
    for (int i = tid; i < 128 * 48; i += NT) {
        int t = i / 48, c4 = (i % 48) * 4;
        float4 v = *(const float4*)(x + ((size_t)(b * Tn + t) * Nn + n) * CIN + c4);
        __half2* dst = (__half2*)(xs + t * XS_PITCH + c4);
        dst[0] = __floats2half2_rn(v.x, v.y);
        dst[1] = __floats2half2_rn(v.z, v.w);
    }
    __syncthreads();

    float acc[4][4][4];
#pragma unroll
    for (int mi = 0; mi < 4; mi++)
#pragma unroll
        for (int ni = 0; ni < 4; ni++)
#pragma unroll
            for (int r = 0; r < 4; r++) acc[mi][ni][r] = 0.f;

    // ================= p0 mainloop (h = x @ W_eff) =================
#pragma unroll 1
    for (int kc = 0; kc < 6; kc++) {
        if (kc < 5) {
            stage(0, kc + 1, (kc + 1) & 1);
            asm volatile("cp.async.wait_group 1;\n");
        } else {
            asm volatile("cp.async.wait_group 0;\n");
        }
        __syncthreads();
        const uint32_t bsel = (uint32_t)((kc & 1) * BS_HALF);
#pragma unroll
        for (int ks = 0; ks < 2; ks++) {
            const uint32_t kbb = (uint32_t)((kc * 32 + ks * 16) * 2);
            uint32_t afr[4][4];
            uint32_t bfr[4][2];
#pragma unroll
            for (int mi = 0; mi < 4; mi++)
                ldsm_x4(afr[mi][0], afr[mi][1], afr[mi][2], afr[mi][3], addrA[mi] + kbb);
#pragma unroll
            for (int pp = 0; pp < 2; pp++)
                ldsm_x4(bfr[pp * 2][0], bfr[pp * 2][1], bfr[pp * 2 + 1][0], bfr[pp * 2 + 1][1],
                        addrB[pp] + bsel + (uint32_t)(ks * 32));
#pragma unroll
            for (int ni = 0; ni < 4; ni++)
#pragma unroll
                for (int mi = 0; mi < 4; mi++)
                    mma16816(acc[mi][ni], afr[mi], bfr[ni]);
        }
        __syncthreads();
    }

    // prefetch first p1 chunk while epilogue runs
    stage(1, 0, 0);

    // ---- p0 epilogue: write h into hbuf[t][o] ----
#pragma unroll
    for (int mi = 0; mi < 4; mi++) {
        int t0e = wm * 64 + mi * 16 + g;
#pragma unroll
        for (int ni = 0; ni < 4; ni++) {
            int o0 = wn * 32 + ni * 8 + 2 * q;
            *(float2*)(hbuf + t0e * HB_PITCH + o0)       = make_float2(acc[mi][ni][0], acc[mi][ni][1]);
            *(float2*)(hbuf + (t0e + 8) * HB_PITCH + o0) = make_float2(acc[mi][ni][2], acc[mi][ni][3]);
        }
    }
    __syncthreads();

    // ---- conv setup: thread = (channel, t-half); preload boundaries ----
    const int o = tid & 255, hf = tid >> 8;
    const int ct0 = hf * 64, ct1 = ct0 + 64;
    const float w0 = convw[o * 3], w1 = convw[o * 3 + 1], w2 = convw[o * 3 + 2];
    float cprev = (ct0 == 0) ? 0.f : hbuf[(ct0 - 1) * HB_PITCH + o];
    float ccur  = hbuf[ct0 * HB_PITCH + o];
    float cbnd  = (ct1 == Tn) ? 0.f : hbuf[ct1 * HB_PITCH + o];
    float cs = 0.f, cs2 = 0.f;
    int tc = ct0;

    // zero acc for p1
#pragma unroll
    for (int mi = 0; mi < 4; mi++)
#pragma unroll
        for (int ni = 0; ni < 4; ni++)
#pragma unroll
            for (int r = 0; r < 4; r++) acc[mi][ni][r] = 0.f;

    // ================= p1 mainloop (res = x @ W_res) + conv interleave =================
#pragma unroll 1
    for (int kc = 0; kc < 6; kc++) {
        if (kc < 5) {
            stage(1, kc + 1, (kc + 1) & 1);
            asm volatile("cp.async.wait_group 1;\n");
        } else {
            asm volatile("cp.async.wait_group 0;\n");
        }
        __syncthreads();
        const uint32_t bsel = (uint32_t)((kc & 1) * BS_HALF);
#pragma unroll
        for (int ks = 0; ks < 2; ks++) {
            const uint32_t kbb = (uint32_t)((kc * 32 + ks * 16) * 2);
            uint32_t afr[4][4];
            uint32_t bfr[4][2];
#pragma unroll
            for (int mi = 0; mi < 4; mi++)
                ldsm_x4(afr[mi][0], afr[mi][1], afr[mi][2], afr[mi][3], addrA[mi] + kbb);
#pragma unroll
            for (int pp = 0; pp < 2; pp++)
                ldsm_x4(bfr[pp * 2][0], bfr[pp * 2][1], bfr[pp * 2 + 1][0], bfr[pp * 2 + 1][1],
                        addrB[pp] + bsel + (uint32_t)(ks * 32));
#pragma unroll
            for (int ni = 0; ni < 4; ni++)
#pragma unroll
                for (int mi = 0; mi < 4; mi++)
                    mma16816(acc[mi][ni], afr[mi], bfr[ni]);
        }
        // ---- conv slice (fills mma shadow; touches only hbuf) ----
        {
            int te = tc + 11; if (te > ct1) te = ct1;
            for (int t = tc; t < te; t++) {
                float nxt = (t == ct1 - 1) ? cbnd : hbuf[(t + 1) * HB_PITCH + o];
                float v = w0 * cprev + w1 * ccur + w2 * nxt;
                hbuf[t * HB_PITCH + o] = v;
                cs += v; cs2 += v * v;
                cprev = ccur; ccur = nxt;
            }
            tc = te;
        }
        __syncthreads();
    }

    // ---- GN stats finalize ----
#pragma unroll
    for (int off = 16; off; off >>= 1) {
        cs  += __shfl_xor_sync(0xFFFFFFFFu, cs,  off);
        cs2 += __shfl_xor_sync(0xFFFFFFFFu, cs2, off);
    }
    if (lane == 0) { s_gn[warp][0] = cs; s_gn[warp][1] = cs2; }
    __syncthreads();
    if (hf == 0) {
        const int grp = warp & 7;
        float gs  = s_gn[grp][0] + s_gn[grp + 8][0];
        float gs2 = s_gn[grp][1] + s_gn[grp + 8][1];
        const float inv = 1.f / (32.f * Tn);
        float mu = gs * inv;
        float var = gs2 * inv - mu * mu;
        float rstd = rsqrtf(var + 1e-5f);
        float ga = gng[o] * rstd;
        chA[o] = ga;
        chB[o] = gnb[o] - mu * ga;
    }
    __syncthreads();

    // ---- preload LN gamma/beta for our 4 columns ----
    float2 lg2[4], lb2[4];
#pragma unroll
    for (int ni = 0; ni < 4; ni++) {
        int o0 = wn * 32 + ni * 8 + 2 * q;
        lg2[ni] = *(const float2*)(lng + o0);
        lb2[ni] = *(const float2*)(lnb + o0);
    }

    // ---- fold: v = h*ga + gb + res (in regs) + LN partial sums ----
#pragma unroll
    for (int mi = 0; mi < 4; mi++) {
#pragma unroll
        for (int half = 0; half < 2; half++) {
            int t = wm * 64 + mi * 16 + g + half * 8;
            float su = 0.f, sq = 0.f;
#pragma unroll
            for (int ni = 0; ni < 4; ni++) {
                int o0 = wn * 32 + ni * 8 + 2 * q;
                float2 hv = *(const float2*)(hbuf + t * HB_PITCH + o0);
                int r = half * 2;
                float v0 = hv.x * chA[o0]     + chB[o0]     + acc[mi][ni][r];
                float v1 = hv.y * chA[o0 + 1] + chB[o0 + 1] + acc[mi][ni][r + 1];
                acc[mi][ni][r] = v0; acc[mi][ni][r + 1] = v1;
                su += v0 + v1; sq += v0 * v0 + v1 * v1;
            }
            su += __shfl_xor_sync(0xFFFFFFFFu, su, 1);
            su += __shfl_xor_sync(0xFFFFFFFFu, su, 2);
            sq += __shfl_xor_sync(0xFFFFFFFFu, sq, 1);
            sq += __shfl_xor_sync(0xFFFFFFFFu, sq, 2);
            if (q == 0) *(float2*)(part + (t * 8 + wn) * 2) = make_float2(su, sq);
        }
    }
    __syncthreads();
    if (tid < Tn) {
        float su = 0.f, sq = 0.f;
#pragma unroll
        for (int w = 0; w < 8; w++) {
            float2 p = *(const float2*)(part + (tid * 8 + w) * 2);
            su += p.x; sq += p.y;
        }
        float mu = su * (1.f / 256.f);
        float var = sq * (1.f / 256.f) - mu * mu;
        *(float2*)(lnstat + tid * 2) = make_float2(mu, rsqrtf(var + 1e-5f));
    }
    __syncthreads();

    // ---- apply LN + GELU from regs, direct store ----
#pragma unroll
    for (int mi = 0; mi < 4; mi++) {
#pragma unroll
        for (int half = 0; half < 2; half++) {
            int t = wm * 64 + mi * 16 + g + half * 8;
            float2 st = *(const float2*)(lnstat + t * 2);
            float mu = st.x, rs = st.y;
            float* ob = out + ((size_t)(b * Tn + t) * Nn + n) * COUT;
            int r = half * 2;
#pragma unroll
            for (int ni = 0; ni < 4; ni++) {
                int o0 = wn * 32 + ni * 8 + 2 * q;
                float y0 = (acc[mi][ni][r]     - mu) * rs * lg2[ni].x + lb2[ni].x;
                float y1 = (acc[mi][ni][r + 1] - mu) * rs * lg2[ni].y + lb2[ni].y;
                *(float2*)(ob + o0) = make_float2(gelu_fast(y0), gelu_fast(y1));
            }
        }
    }
}

// ---------------- launch ----------------
extern "C" void kernel_launch(void* const* d_in, const int* in_sizes, int n_in,
                              void* d_out, int out_size) {
    const float* x     = (const float*)d_in[0];
    const float* A     = (const float*)d_in[1];
    const float* dw    = (const float*)d_in[2];
    const float* adj   = (const float*)d_in[3];
    const float* Wpw   = (const float*)d_in[4];
    const float* convw = (const float*)d_in[5];
    const float* gng   = (const float*)d_in[6];
    const float* gnb   = (const float*)d_in[7];
    const float* lng   = (const float*)d_in[8];
    const float* lnb   = (const float*)d_in[9];
    const float* Wres  = (const float*)d_in[10];
    float* out = (float*)d_out;

    cudaFuncSetAttribute(k_fused, cudaFuncAttributeMaxDynamicSharedMemorySize, SMEM_TOTAL);

    int total8 = Nn * 512 * 24;
    k_wh<<<(total8 + 255) / 256, 256>>>(A, adj, dw, Wpw, Wres);
    k_fused<<<dim3(Nn, Bsz), NT, SMEM_TOTAL>>>(x, convw, gng, gnb, lng, lnb, out);
}